// round 7
// baseline (speedup 1.0000x reference)
#include <cuda_runtime.h>
#include <utility>

// =====================================================================
// HiPPO-LegS reconstruction:  out = sum_{k=1..256} coef[k-1]*sqrt(2k+1)*P_k(x)
// x = 2*t/curr_t - 1, 524288 points.
//
// Scaled Clenshaw backward recurrence, compile-time constants:
//   tt = FFMA(b2, -beta_imm, c)   (imm form)
//   b1 = FFMA(b1, x, tt)          (reg form)
// R7 shape: V=2 elems/thread, TPB=64 -> 4096 blocks / 8192 warps:
//  - 27.7 blocks/SM -> ~4% SM imbalance (vs 16% at 1024 blocks)
//  - 13.8 warps/SMSP -> LDS(29cyc)+FFMA(4cyc) latency fully hidden
//  - body ~20.6KB SASS -> fits 32KB L1.5 I$ (R5's 37KB did not)
// FFMA2/f32x2 ruled out by R6: same lane throughput as scalar FFMA.
// =====================================================================

#define NDEG 256
#define V    2
#define TPB  64

// ---------------- compile-time scaling machinery ----------------

__host__ __device__ constexpr double c_TH()  { return 9.5367431640625e-07; } // 2^-20
__host__ __device__ constexpr double c_RHO() { return 1048576.0; }           // 2^20

__host__ __device__ constexpr double Ak(int k) { return (2.0 * k + 1.0) / (double)(k + 1); }
__host__ __device__ constexpr double Bk(int k) { return (double)k / (double)(k + 1); }

__host__ __device__ constexpr double s_of(int k) {
    if (k >= NDEG + 1) return 1.0;
    double s = 1.0;
    for (int j = NDEG; j >= k; --j) {
        s /= Ak(j);
        if (s < c_TH()) s *= c_RHO();
    }
    return s;
}

__host__ __device__ constexpr bool boosted(int k) {
    if (k >= NDEG + 1) return false;
    double s = 1.0;
    for (int j = NDEG; j >= k; --j) {
        s /= Ak(j);
        if (s < c_TH()) {
            s *= c_RHO();
            if (j == k) return true;
        }
    }
    return false;
}

__host__ __device__ constexpr double beta_of(int k) {
    return Bk(k + 1) * s_of(k) / s_of(k + 2);
}

__host__ __device__ constexpr double csqrt(double v) {
    double g = v < 1.0 ? 1.0 : v;
    for (int i = 0; i < 100; ++i) g = 0.5 * (g + v / g);
    return g;
}

__host__ __device__ constexpr float g_of(int k) {
    return (float)(s_of(k) * csqrt(2.0 * k + 1.0));
}

struct GTab { float v[NDEG + 1]; };
template <size_t... I>
constexpr GTab make_gtab(std::index_sequence<I...>) {
    return GTab{{ (I == 0 ? 0.0f : g_of((int)I))... }};
}
__constant__ GTab G = make_gtab(std::make_index_sequence<NDEG + 1>{});

// ---------------- Clenshaw steps, chunked template expansion ----------------
// Invariant entering step K: b1[v] = s_{K+1}*b_{K+1}, b2[v] = s_{K+2}*b_{K+2}

template <int K>
__device__ __forceinline__ void one_step(const float* __restrict__ sc,
                                         const float (&x)[V], const float (&xr)[V],
                                         float (&b1)[V], float (&b2)[V]) {
    constexpr float BETA  = (float)(-beta_of(K));  // immediate multiplier
    constexpr bool  BOOST = boosted(K);
    const float c = sc[K];                          // LDS broadcast
#pragma unroll
    for (int v = 0; v < V; ++v) {
        float o1 = b1[v];
        float tt = fmaf(b2[v], BETA, c);               // FFMA imm
        b1[v]    = fmaf(o1, BOOST ? xr[v] : x[v], tt); // FFMA reg
        b2[v]    = o1;                                 // rename (free, unrolled)
    }
}

template <int K, size_t... J>
__device__ __forceinline__ void chunk_steps(std::index_sequence<J...>,
                                            const float* __restrict__ sc,
                                            const float (&x)[V], const float (&xr)[V],
                                            float (&b1)[V], float (&b2)[V]) {
    (one_step<K - (int)J>(sc, x, xr, b1, b2), ...);
}

template <int K>
struct Step {
    static constexpr int CH = (K + 1 < 16) ? (K + 1) : 16;
    static __device__ __forceinline__ void run(const float* __restrict__ sc,
                                               const float (&x)[V], const float (&xr)[V],
                                               float (&b1)[V], float (&b2)[V]) {
        chunk_steps<K>(std::make_index_sequence<CH>{}, sc, x, xr, b1, b2);
        Step<K - CH>::run(sc, x, xr, b1, b2);
    }
};
template <>
struct Step<-1> {
    static __device__ __forceinline__ void run(const float* __restrict__,
                                               const float (&)[V], const float (&)[V],
                                               float (&)[V], float (&)[V]) {}
};

// ---------------- kernel ----------------

__global__ __launch_bounds__(TPB) void hippo_clenshaw_kernel(
    const float* __restrict__ t, const float* __restrict__ coef,
    const int* __restrict__ ctp, float* __restrict__ out, int n)
{
    __shared__ float sc[NDEG + 1];
    for (int i = threadIdx.x; i <= NDEG; i += TPB)
        sc[i] = (i == 0) ? 0.0f : G.v[i] * __ldg(coef + i - 1);
    __syncthreads();

    // curr_t: tolerate int32 payload (expected) or a float bit pattern
    float ct = 1.0f;
    if (ctp) {
        int iv   = *ctp;
        float fv = __int_as_float(iv);
        ct = (iv > 0 && iv < (1 << 20)) ? (float)iv : fv;
    }
    const float sc2 = 2.0f / ct;

    const long long base = ((long long)blockIdx.x * TPB + threadIdx.x) * V;
    if (base >= n) return;

    constexpr float INVS0 = (float)(1.0 / s_of(0));
    constexpr float RHOF  = (float)c_RHO();

    float tv[V];
    if (base + V <= n) {
        float2 ta = *reinterpret_cast<const float2*>(t + base);
        tv[0] = ta.x; tv[1] = ta.y;
    } else {
#pragma unroll
        for (int v = 0; v < V; ++v) {
            long long idx = base + v;
            tv[v] = (idx < n) ? t[idx] : 0.0f;
        }
    }

    float x[V], xr[V], b1[V], b2[V];
#pragma unroll
    for (int v = 0; v < V; ++v) {
        x[v]  = fmaf(tv[v], sc2, -1.0f);
        xr[v] = x[v] * RHOF;   // exact pow2 pre-scale for boost steps
        b1[v] = 0.0f;
        b2[v] = 0.0f;
    }

    Step<NDEG>::run(sc, x, xr, b1, b2);

    if (base + V <= n) {
        *reinterpret_cast<float2*>(out + base) =
            make_float2(b1[0] * INVS0, b1[1] * INVS0);
    } else {
#pragma unroll
        for (int v = 0; v < V; ++v) {
            long long idx = base + v;
            if (idx < n) out[idx] = b1[v] * INVS0;
        }
    }
}

// ---------------- launch ----------------

extern "C" void kernel_launch(void* const* d_in, const int* in_sizes, int n_in,
                              void* d_out, int out_size)
{
    // Identify inputs by size: big -> t, 1 -> curr_t, remaining -> coef
    int ti = -1, ci = -1, si = -1;
    for (int i = 0; i < n_in; ++i) {
        if (in_sizes[i] == out_size && ti < 0)      ti = i;
        else if (in_sizes[i] == 1 && si < 0)        si = i;
        else if (ci < 0)                            ci = i;
    }
    if (ti < 0) ti = 0;
    if (ci < 0) ci = (n_in > 1 ? 1 : 0);

    const float* t    = (const float*)d_in[ti];
    const float* coef = (const float*)d_in[ci];
    const int*   ct   = (si >= 0) ? (const int*)d_in[si] : nullptr;

    int n = out_size;
    int elems_per_block = TPB * V;
    int blocks = (n + elems_per_block - 1) / elems_per_block;
    hippo_clenshaw_kernel<<<blocks, TPB>>>(t, coef, ct, (float*)d_out, n);
}

// round 8
// speedup vs baseline: 1.2137x; 1.2137x over previous
#include <cuda_runtime.h>
#include <utility>

// =====================================================================
// HiPPO-LegS reconstruction:  out = sum_{k=1..256} coef[k-1]*sqrt(2k+1)*P_k(x)
// x = 2*t/curr_t - 1, 524288 points.
//
// Scaled Clenshaw backward recurrence, compile-time constants:
//   tt = FFMA(b2, -beta_imm, c)   (imm multiplier form)
//   b1 = FFMA(b1, x, tt)          (reg form)
// R8: V=4 elems/thread (R5's proven sweet spot) with two efficiency fixes:
//  - c-table stored REVERSED in smem; one LDS.128 fetches constants for
//    4 consecutive degrees (LDS wavefronts /4, issues per 4 steps 20->17)
//  - TPB=64 -> 2048 blocks: 14-vs-13 blocks/SM (~1% imbalance) instead of
//    R5's 7-vs-6 (~16%), same 6.9 warps/SMSP.
// f32x2 ruled out (R6): packed FFMA2 retires at scalar lane rate.
// V=2 ruled out (R7): per-warp overhead scales with warp count.
// =====================================================================

#define NDEG 256
#define V    4
#define TPB  64

// ---------------- compile-time scaling machinery ----------------

__host__ __device__ constexpr double c_TH()  { return 9.5367431640625e-07; } // 2^-20
__host__ __device__ constexpr double c_RHO() { return 1048576.0; }           // 2^20

__host__ __device__ constexpr double Ak(int k) { return (2.0 * k + 1.0) / (double)(k + 1); }
__host__ __device__ constexpr double Bk(int k) { return (double)k / (double)(k + 1); }

__host__ __device__ constexpr double s_of(int k) {
    if (k >= NDEG + 1) return 1.0;
    double s = 1.0;
    for (int j = NDEG; j >= k; --j) {
        s /= Ak(j);
        if (s < c_TH()) s *= c_RHO();
    }
    return s;
}

__host__ __device__ constexpr bool boosted(int k) {
    if (k >= NDEG + 1) return false;
    double s = 1.0;
    for (int j = NDEG; j >= k; --j) {
        s /= Ak(j);
        if (s < c_TH()) {
            s *= c_RHO();
            if (j == k) return true;
        }
    }
    return false;
}

__host__ __device__ constexpr double beta_of(int k) {
    return Bk(k + 1) * s_of(k) / s_of(k + 2);
}

__host__ __device__ constexpr double csqrt(double v) {
    double g = v < 1.0 ? 1.0 : v;
    for (int i = 0; i < 100; ++i) g = 0.5 * (g + v / g);
    return g;
}

__host__ __device__ constexpr float g_of(int k) {
    return (float)(s_of(k) * csqrt(2.0 * k + 1.0));
}

struct GTab { float v[NDEG + 1]; };
template <size_t... I>
constexpr GTab make_gtab(std::index_sequence<I...>) {
    return GTab{{ (I == 0 ? 0.0f : g_of((int)I))... }};
}
__constant__ GTab G = make_gtab(std::make_index_sequence<NDEG + 1>{});

// ---------------- Clenshaw steps ----------------
// Invariant entering step K: b1[v] = s_{K+1}*b_{K+1}, b2[v] = s_{K+2}*b_{K+2}
// c passed by value (pre-fetched via LDS.128 per 4 degrees).

template <int K>
__device__ __forceinline__ void one_step(float c,
                                         const float (&x)[V], const float (&xr)[V],
                                         float (&b1)[V], float (&b2)[V]) {
    constexpr float BETA  = (float)(-beta_of(K));  // immediate multiplier
    constexpr bool  BOOST = boosted(K);
#pragma unroll
    for (int v = 0; v < V; ++v) {
        float o1 = b1[v];
        float tt = fmaf(b2[v], BETA, c);               // FFMA imm
        b1[v]    = fmaf(o1, BOOST ? xr[v] : x[v], tt); // FFMA reg
        b2[v]    = o1;                                 // rename (free, unrolled)
    }
}

// Group G handles degrees 256-4G, 255-4G, 254-4G, 253-4G with one LDS.128.
// smem layout (reversed): scl[m] = c(256 - m), float4-aligned.
template <int Gr>
__device__ __forceinline__ void group4(const float* __restrict__ scl,
                                       const float (&x)[V], const float (&xr)[V],
                                       float (&b1)[V], float (&b2)[V]) {
    const float4 cc = *reinterpret_cast<const float4*>(scl + 4 * Gr); // LDS.128
    one_step<NDEG - 4 * Gr    >(cc.x, x, xr, b1, b2);
    one_step<NDEG - 4 * Gr - 1>(cc.y, x, xr, b1, b2);
    one_step<NDEG - 4 * Gr - 2>(cc.z, x, xr, b1, b2);
    one_step<NDEG - 4 * Gr - 3>(cc.w, x, xr, b1, b2);
}

template <size_t... Gs>
__device__ __forceinline__ void all_groups(std::index_sequence<Gs...>,
                                           const float* __restrict__ scl,
                                           const float (&x)[V], const float (&xr)[V],
                                           float (&b1)[V], float (&b2)[V]) {
    (group4<(int)Gs>(scl, x, xr, b1, b2), ...);
}

// ---------------- kernel ----------------

__global__ __launch_bounds__(TPB) void hippo_clenshaw_kernel(
    const float* __restrict__ t, const float* __restrict__ coef,
    const int* __restrict__ ctp, float* __restrict__ out, int n)
{
    // Reversed, float4-aligned constant table: scl[m] = c(256-m), m=0..259.
    __shared__ __align__(16) float scl[NDEG + 4];
    for (int m = threadIdx.x; m < NDEG + 4; m += TPB) {
        int k = NDEG - m;
        scl[m] = (k >= 1) ? G.v[k] * __ldg(coef + k - 1) : 0.0f;
    }
    __syncthreads();

    // curr_t: tolerate int32 payload (expected) or a float bit pattern
    float ct = 1.0f;
    if (ctp) {
        int iv   = *ctp;
        float fv = __int_as_float(iv);
        ct = (iv > 0 && iv < (1 << 20)) ? (float)iv : fv;
    }
    const float sc2 = 2.0f / ct;

    const long long base = ((long long)blockIdx.x * TPB + threadIdx.x) * V;
    if (base >= n) return;

    constexpr float INVS0 = (float)(1.0 / s_of(0));
    constexpr float RHOF  = (float)c_RHO();

    float tv[V];
    if (base + V <= n) {
        float4 ta = *reinterpret_cast<const float4*>(t + base);
        tv[0] = ta.x; tv[1] = ta.y; tv[2] = ta.z; tv[3] = ta.w;
    } else {
#pragma unroll
        for (int v = 0; v < V; ++v) {
            long long idx = base + v;
            tv[v] = (idx < n) ? t[idx] : 0.0f;
        }
    }

    float x[V], xr[V], b1[V], b2[V];
#pragma unroll
    for (int v = 0; v < V; ++v) {
        x[v]  = fmaf(tv[v], sc2, -1.0f);
        xr[v] = x[v] * RHOF;   // exact pow2 pre-scale for boost steps
        b1[v] = 0.0f;
        b2[v] = 0.0f;
    }

    // Degrees 256..1 in 64 groups of 4 (one LDS.128 each)
    all_groups(std::make_index_sequence<NDEG / 4>{}, scl, x, xr, b1, b2);
    // Final degree 0: c_0 = 0
    one_step<0>(0.0f, x, xr, b1, b2);

    if (base + V <= n) {
        *reinterpret_cast<float4*>(out + base) =
            make_float4(b1[0] * INVS0, b1[1] * INVS0,
                        b1[2] * INVS0, b1[3] * INVS0);
    } else {
#pragma unroll
        for (int v = 0; v < V; ++v) {
            long long idx = base + v;
            if (idx < n) out[idx] = b1[v] * INVS0;
        }
    }
}

// ---------------- launch ----------------

extern "C" void kernel_launch(void* const* d_in, const int* in_sizes, int n_in,
                              void* d_out, int out_size)
{
    // Identify inputs by size: big -> t, 1 -> curr_t, remaining -> coef
    int ti = -1, ci = -1, si = -1;
    for (int i = 0; i < n_in; ++i) {
        if (in_sizes[i] == out_size && ti < 0)      ti = i;
        else if (in_sizes[i] == 1 && si < 0)        si = i;
        else if (ci < 0)                            ci = i;
    }
    if (ti < 0) ti = 0;
    if (ci < 0) ci = (n_in > 1 ? 1 : 0);

    const float* t    = (const float*)d_in[ti];
    const float* coef = (const float*)d_in[ci];
    const int*   ct   = (si >= 0) ? (const int*)d_in[si] : nullptr;

    int n = out_size;
    int elems_per_block = TPB * V;
    int blocks = (n + elems_per_block - 1) / elems_per_block;
    hippo_clenshaw_kernel<<<blocks, TPB>>>(t, coef, ct, (float*)d_out, n);
}

// round 9
// speedup vs baseline: 1.3769x; 1.1345x over previous
#include <cuda_runtime.h>
#include <utility>

// =====================================================================
// HiPPO-LegS reconstruction:  out = sum_{k=1..256} coef[k-1]*sqrt(2k+1)*P_k(x)
// x = 2*t/curr_t - 1, 524288 points.
//
// Scaled Clenshaw backward recurrence, compile-time constants:
//   tt = FFMA(b2, -beta_imm, c)   (imm multiplier form)
//   b1 = FFMA(b1, x, tt)          (reg form)
// R9 = R5 (V=4, TPB=128, 1024 blocks: proven best) plus exactly:
//  - c-table REVERSED + float4-aligned in smem; one LDS.128 serves 4
//    consecutive degrees -> issues/elem-degree 2.25 -> 2.06, MIO /4.
//    (R8 tested this confounded with TPB=64, whose 2-warp blocks stall
//    on the prologue; here TPB stays 128.)
//  - 1/s0 output scale folded into the c-table (Clenshaw is linear in c)
//    -> epilogue FMULs eliminated.
// Ruled out: f32x2 (R6, scalar-rate), V=2 (R7, overhead scales with
// warps), TPB=64 (R7/R8 prologue stall).
// =====================================================================

#define NDEG 256
#define V    4
#define TPB  128

// ---------------- compile-time scaling machinery ----------------

__host__ __device__ constexpr double c_TH()  { return 9.5367431640625e-07; } // 2^-20
__host__ __device__ constexpr double c_RHO() { return 1048576.0; }           // 2^20

__host__ __device__ constexpr double Ak(int k) { return (2.0 * k + 1.0) / (double)(k + 1); }
__host__ __device__ constexpr double Bk(int k) { return (double)k / (double)(k + 1); }

__host__ __device__ constexpr double s_of(int k) {
    if (k >= NDEG + 1) return 1.0;
    double s = 1.0;
    for (int j = NDEG; j >= k; --j) {
        s /= Ak(j);
        if (s < c_TH()) s *= c_RHO();
    }
    return s;
}

__host__ __device__ constexpr bool boosted(int k) {
    if (k >= NDEG + 1) return false;
    double s = 1.0;
    for (int j = NDEG; j >= k; --j) {
        s /= Ak(j);
        if (s < c_TH()) {
            s *= c_RHO();
            if (j == k) return true;
        }
    }
    return false;
}

__host__ __device__ constexpr double beta_of(int k) {
    return Bk(k + 1) * s_of(k) / s_of(k + 2);
}

__host__ __device__ constexpr double csqrt(double v) {
    double g = v < 1.0 ? 1.0 : v;
    for (int i = 0; i < 100; ++i) g = 0.5 * (g + v / g);
    return g;
}

// g'_k = (s_k / s_0) * sqrt(2k+1): coefficient scale with the 1/s0 output
// normalization folded in (Clenshaw output is linear in the c-vector).
__host__ __device__ constexpr float g_of(int k) {
    return (float)((s_of(k) / s_of(0)) * csqrt(2.0 * k + 1.0));
}

struct GTab { float v[NDEG + 1]; };
template <size_t... I>
constexpr GTab make_gtab(std::index_sequence<I...>) {
    return GTab{{ (I == 0 ? 0.0f : g_of((int)I))... }};
}
__constant__ GTab G = make_gtab(std::make_index_sequence<NDEG + 1>{});

// ---------------- Clenshaw steps ----------------
// Invariant entering step K: b1[v] = (s_{K+1}/s_0)*b_{K+1} etc. (uniform
// rescale by 1/s0 throughout; beta/boost constants unaffected).
// c passed by value (pre-fetched via one LDS.128 per 4 degrees).

template <int K>
__device__ __forceinline__ void one_step(float c,
                                         const float (&x)[V], const float (&xr)[V],
                                         float (&b1)[V], float (&b2)[V]) {
    constexpr float BETA  = (float)(-beta_of(K));  // immediate multiplier
    constexpr bool  BOOST = boosted(K);
#pragma unroll
    for (int v = 0; v < V; ++v) {
        float o1 = b1[v];
        float tt = fmaf(b2[v], BETA, c);               // FFMA imm
        b1[v]    = fmaf(o1, BOOST ? xr[v] : x[v], tt); // FFMA reg
        b2[v]    = o1;                                 // rename (free, unrolled)
    }
}

// Group Gr handles degrees 256-4Gr .. 253-4Gr with one aligned LDS.128.
// smem layout (reversed): scl[m] = c(256 - m).
template <int Gr>
__device__ __forceinline__ void group4(const float* __restrict__ scl,
                                       const float (&x)[V], const float (&xr)[V],
                                       float (&b1)[V], float (&b2)[V]) {
    const float4 cc = *reinterpret_cast<const float4*>(scl + 4 * Gr); // LDS.128
    one_step<NDEG - 4 * Gr    >(cc.x, x, xr, b1, b2);
    one_step<NDEG - 4 * Gr - 1>(cc.y, x, xr, b1, b2);
    one_step<NDEG - 4 * Gr - 2>(cc.z, x, xr, b1, b2);
    one_step<NDEG - 4 * Gr - 3>(cc.w, x, xr, b1, b2);
}

template <size_t... Gs>
__device__ __forceinline__ void all_groups(std::index_sequence<Gs...>,
                                           const float* __restrict__ scl,
                                           const float (&x)[V], const float (&xr)[V],
                                           float (&b1)[V], float (&b2)[V]) {
    (group4<(int)Gs>(scl, x, xr, b1, b2), ...);
}

// ---------------- kernel ----------------

__global__ __launch_bounds__(TPB) void hippo_clenshaw_kernel(
    const float* __restrict__ t, const float* __restrict__ coef,
    const int* __restrict__ ctp, float* __restrict__ out, int n)
{
    // Reversed, float4-aligned constant table: scl[m] = c(256-m), m=0..259.
    __shared__ __align__(16) float scl[NDEG + 4];
    for (int m = threadIdx.x; m < NDEG + 4; m += TPB) {
        int k = NDEG - m;
        scl[m] = (k >= 1) ? G.v[k] * __ldg(coef + k - 1) : 0.0f;
    }
    __syncthreads();

    // curr_t: tolerate int32 payload (expected) or a float bit pattern
    float ct = 1.0f;
    if (ctp) {
        int iv   = *ctp;
        float fv = __int_as_float(iv);
        ct = (iv > 0 && iv < (1 << 20)) ? (float)iv : fv;
    }
    const float sc2 = 2.0f / ct;

    const long long base = ((long long)blockIdx.x * TPB + threadIdx.x) * V;
    if (base >= n) return;

    constexpr float RHOF = (float)c_RHO();

    float tv[V];
    if (base + V <= n) {
        float4 ta = *reinterpret_cast<const float4*>(t + base);
        tv[0] = ta.x; tv[1] = ta.y; tv[2] = ta.z; tv[3] = ta.w;
    } else {
#pragma unroll
        for (int v = 0; v < V; ++v) {
            long long idx = base + v;
            tv[v] = (idx < n) ? t[idx] : 0.0f;
        }
    }

    float x[V], xr[V], b1[V], b2[V];
#pragma unroll
    for (int v = 0; v < V; ++v) {
        x[v]  = fmaf(tv[v], sc2, -1.0f);
        xr[v] = x[v] * RHOF;   // exact pow2 pre-scale for boost steps
        b1[v] = 0.0f;
        b2[v] = 0.0f;
    }

    // Degrees 256..1 in 64 groups of 4 (one LDS.128 each)
    all_groups(std::make_index_sequence<NDEG / 4>{}, scl, x, xr, b1, b2);
    // Final degree 0: c_0 = 0
    one_step<0>(0.0f, x, xr, b1, b2);

    // 1/s0 already folded into the c-table: b1 is the final answer.
    if (base + V <= n) {
        *reinterpret_cast<float4*>(out + base) =
            make_float4(b1[0], b1[1], b1[2], b1[3]);
    } else {
#pragma unroll
        for (int v = 0; v < V; ++v) {
            long long idx = base + v;
            if (idx < n) out[idx] = b1[v];
        }
    }
}

// ---------------- launch ----------------

extern "C" void kernel_launch(void* const* d_in, const int* in_sizes, int n_in,
                              void* d_out, int out_size)
{
    // Identify inputs by size: big -> t, 1 -> curr_t, remaining -> coef
    int ti = -1, ci = -1, si = -1;
    for (int i = 0; i < n_in; ++i) {
        if (in_sizes[i] == out_size && ti < 0)      ti = i;
        else if (in_sizes[i] == 1 && si < 0)        si = i;
        else if (ci < 0)                            ci = i;
    }
    if (ti < 0) ti = 0;
    if (ci < 0) ci = (n_in > 1 ? 1 : 0);

    const float* t    = (const float*)d_in[ti];
    const float* coef = (const float*)d_in[ci];
    const int*   ct   = (si >= 0) ? (const int*)d_in[si] : nullptr;

    int n = out_size;
    int elems_per_block = TPB * V;
    int blocks = (n + elems_per_block - 1) / elems_per_block;
    hippo_clenshaw_kernel<<<blocks, TPB>>>(t, coef, ct, (float*)d_out, n);
}